// round 17
// baseline (speedup 1.0000x reference)
#include <cuda_runtime.h>
#include <cuda_bf16.h>
#include <cstdint>

#define NROWS 50000
#define KNB   32
#define CDIM  128
#define TOPK  16
#define GR    128                         // rows per GEMM block
#define NGB   ((NROWS + GR - 1) / GR)     // 391
#define GEMM_SMEM (128*128*4 + 2*2*16*128*4)   // As 64KB + B 32KB = 98304

// ---------------- scratch (device globals; no allocation) ----------------
__device__ __align__(16) float g_M [CDIM * CDIM];     // Wq^T @ Wk
__device__ __align__(16) float g_Ws[CDIM * CDIM];     // triu(W) + triu(W)^T
__device__ __align__(16) float g_qM[(size_t)NROWS * CDIM];  // feat @ M
__device__ __align__(16) float g_fW[(size_t)NROWS * CDIM];  // feat @ Ws
__device__ __align__(16) float g_scores[(size_t)NROWS * KNB];
__device__ int g_colmask[KNB];
__device__ int g_mask_narrow;   // 1 -> mask elements are 1 byte; 0 -> 4 bytes

// ---------------- cp.async helpers ----------------
__device__ __forceinline__ void cp_async16(void* smem_dst, const void* gptr) {
    uint32_t s = (uint32_t)__cvta_generic_to_shared(smem_dst);
    asm volatile("cp.async.cg.shared.global [%0], [%1], 16;\n" :: "r"(s), "l"(gptr));
}
__device__ __forceinline__ void cp_async_commit() {
    asm volatile("cp.async.commit_group;\n" ::: "memory");
}
template <int N> __device__ __forceinline__ void cp_async_wait() {
    asm volatile("cp.async.wait_group %0;\n" :: "n"(N) : "memory");
}

// ---------------- K0: prep M, Ws, reset flags ----------------
__global__ void prep_kernel(const float* __restrict__ Wq,
                            const float* __restrict__ Wk,
                            const float* __restrict__ W) {
    int c = blockIdx.x;    // 0..127
    int e = threadIdx.x;   // 0..127
    float acc = 0.f;
#pragma unroll 8
    for (int d = 0; d < CDIM; d++)
        acc += Wq[d * CDIM + c] * Wk[d * CDIM + e];
    g_M[c * CDIM + e] = acc;

    float w = (c <= e) ? W[c * CDIM + e] : W[e * CDIM + c];
    g_Ws[c * CDIM + e] = (c == e) ? 2.f * w : w;

    if (c == 0 && e < KNB) g_colmask[e] = 0;
    if (c == 0 && e == KNB) g_mask_narrow = 0;
}

// ---------------- K0b: sniff knn_mask element width ----------------
__global__ void sniff_kernel(const unsigned int* __restrict__ w) {
    const int nwords = NROWS * KNB / 4;
    int bad = 0;
    for (int i = blockIdx.x * blockDim.x + threadIdx.x; i < nwords;
         i += gridDim.x * blockDim.x) {
        unsigned int v = w[i];
        if (v != 0u && v != 1u && v != 0x3F800000u) bad = 1;
    }
    if (bad) g_mask_narrow = 1;
}

// ---------------- K1: SGEMM v6 (unchanged; ~near FFMA floor) --------
__global__ void __launch_bounds__(512, 1) gemm_kernel(const float* __restrict__ A) {
    extern __shared__ float sm[];
    float* As = sm;              // [128][128]
    float* Bs = sm + 128 * 128;  // M buf0 | M buf1 | W buf0 | W buf1 (2048 f each)

    int tid  = threadIdx.x;
    int half = tid >> 8;
    int t    = tid & 255;
    int rg   = t >> 4;           // rows rg*8 .. rg*8+7
    int cg   = t & 15;           // cols cg*8 .. cg*8+7
    int row0 = blockIdx.x * GR;

    for (int i = tid; i < 4096; i += 512) {
        int r = i >> 5;
        if (row0 + r < NROWS)
            cp_async16((float4*)As + i,
                       (const float4*)A + (size_t)(row0 + r) * 32 + (i & 31));
        else
            ((float4*)As)[i] = make_float4(0.f, 0.f, 0.f, 0.f);
    }
    cp_async16((float4*)(Bs         ) + tid, (const float4*)g_M  + tid);
    cp_async16((float4*)(Bs + 4096  ) + tid, (const float4*)g_Ws + tid);
    cp_async_commit();                                   // G0: A + B0
    cp_async16((float4*)(Bs + 2048  ) + tid, (const float4*)g_M  + 512 + tid);
    cp_async16((float4*)(Bs + 6144  ) + tid, (const float4*)g_Ws + 512 + tid);
    cp_async_commit();                                   // G1: B1
    cp_async_wait<1>();                                  // G0 done
    __syncthreads();

    float acc[8][8];
#pragma unroll
    for (int i = 0; i < 8; i++)
#pragma unroll
        for (int j = 0; j < 8; j++) acc[i][j] = 0.f;

    const float* Bhalf = Bs + half * 4096;

    for (int c = 0; c < 8; c++) {
        const float* Bc = Bhalf + (c & 1) * 2048;
        const float* Ac = As + c * 16;
#pragma unroll
        for (int kk = 0; kk < 16; kk++) {
            float a[8];
#pragma unroll
            for (int i = 0; i < 8; i++)
                a[i] = Ac[(rg * 8 + i) * 128 + kk];
            float4 b0 = *(const float4*)(Bc + kk * 128 + cg * 8);
            float4 b1 = *(const float4*)(Bc + kk * 128 + cg * 8 + 4);
            float b[8] = {b0.x, b0.y, b0.z, b0.w, b1.x, b1.y, b1.z, b1.w};
#pragma unroll
            for (int i = 0; i < 8; i++)
#pragma unroll
                for (int j = 0; j < 8; j++) acc[i][j] += a[i] * b[j];
        }
        __syncthreads();                       // done reading buf c&1
        if (c + 2 < 8) {
            float* dst = Bs + (c & 1) * 2048;  // reuse freed buffer
            cp_async16((float4*)(dst       ) + tid,
                       (const float4*)g_M  + (c + 2) * 512 + tid);
            cp_async16((float4*)(dst + 4096) + tid,
                       (const float4*)g_Ws + (c + 2) * 512 + tid);
            cp_async_commit();
        }
        if (c + 1 < 8) {
            cp_async_wait<1>();                // chunk c+1 resident
            __syncthreads();
        }
    }

    float* __restrict__ Out = half ? g_fW : g_qM;
#pragma unroll
    for (int i = 0; i < 8; i++) {
        int r = row0 + rg * 8 + i;
        if (r < NROWS) {
            float4* p = (float4*)(Out + (size_t)r * 128 + cg * 8);
            p[0] = make_float4(acc[i][0], acc[i][1], acc[i][2], acc[i][3]);
            p[1] = make_float4(acc[i][4], acc[i][5], acc[i][6], acc[i][7]);
        }
    }
}

// ---------------- K2: warp-per-row, single-pass BATCH-PARALLEL online softmax ----
// Per 4-neighbor batch: one rescale (fmax + 1 exp), 4 parallel exps, tree
// accumulate — serial cross-neighbor chain is 8 steps instead of 32.
__global__ void __launch_bounds__(256, 5) main_kernel(
    const float* __restrict__ feat, const float* __restrict__ knn_xyz,
    const float* __restrict__ knn_feat, const void* __restrict__ knn_mask,
    float* __restrict__ out_xyz, float* __restrict__ out_att, float* __restrict__ out_ml)
{
    int tid  = threadIdx.x;
    int warp = tid >> 5;
    int lane = tid & 31;
    int n    = blockIdx.x * 8 + warp;

    const float4* kf4 = reinterpret_cast<const float4*>(knn_feat + (size_t)n * (KNB * CDIM));
    float4 qv = __ldg(reinterpret_cast<const float4*>(g_qM + (size_t)n * CDIM) + lane);
    float4 fv = __ldg(reinterpret_cast<const float4*>(g_fW + (size_t)n * CDIM) + lane);

    // lane j's mask adjust + xyz triplet
    float madj;
    if (g_mask_narrow)
        madj = ((const unsigned char*)knn_mask)[(size_t)n * KNB + lane] ? 0.f : -1e12f;
    else
        madj = ((const unsigned int*)knn_mask)[(size_t)n * KNB + lane] ? 0.f : -1e12f;
    float xj0 = __ldg(&knn_xyz[(size_t)n * 96 + lane * 3    ]);
    float xj1 = __ldg(&knn_xyz[(size_t)n * 96 + lane * 3 + 1]);
    float xj2 = __ldg(&knn_xyz[(size_t)n * 96 + lane * 3 + 2]);

    float myS = 0.f, myMl = 0.f;
    float m_run = -3.0e38f, sum = 0.f;
    float4 acc4 = make_float4(0.f, 0.f, 0.f, 0.f);

#pragma unroll
    for (int b = 0; b < 8; b++) {
        float4 kf[4];
        float s[4], ml[4];
#pragma unroll
        for (int jj = 0; jj < 4; jj++) {
            kf[jj] = __ldg(kf4 + (b * 4 + jj) * 32 + lane);
            s [jj] = kf[jj].x * qv.x + kf[jj].y * qv.y + kf[jj].z * qv.z + kf[jj].w * qv.w;
            ml[jj] = kf[jj].x * fv.x + kf[jj].y * fv.y + kf[jj].z * fv.z + kf[jj].w * fv.w;
        }
#pragma unroll
        for (int o = 16; o; o >>= 1) {
#pragma unroll
            for (int jj = 0; jj < 4; jj++) {
                s [jj] += __shfl_xor_sync(0xffffffffu, s [jj], o);
                ml[jj] += __shfl_xor_sync(0xffffffffu, ml[jj], o);
            }
        }
        // apply mask (warp-uniform), capture own score
#pragma unroll
        for (int jj = 0; jj < 4; jj++) {
            int j = b * 4 + jj;
            s[jj] += __shfl_sync(0xffffffffu, madj, j);
            if (lane == j) { myS = s[jj]; myMl = ml[jj]; }
        }
        // batch-parallel online update: one rescale, 4 parallel exps, tree sum
        float bmax  = fmaxf(fmaxf(s[0], s[1]), fmaxf(s[2], s[3]));
        float m_new = fmaxf(m_run, bmax);
        float sc = __expf(m_run - m_new);
        float e0 = __expf(s[0] - m_new);
        float e1 = __expf(s[1] - m_new);
        float e2 = __expf(s[2] - m_new);
        float e3 = __expf(s[3] - m_new);
        acc4.x = acc4.x * sc + ((e0 * kf[0].x + e1 * kf[1].x) + (e2 * kf[2].x + e3 * kf[3].x));
        acc4.y = acc4.y * sc + ((e0 * kf[0].y + e1 * kf[1].y) + (e2 * kf[2].y + e3 * kf[3].y));
        acc4.z = acc4.z * sc + ((e0 * kf[0].z + e1 * kf[1].z) + (e2 * kf[2].z + e3 * kf[3].z));
        acc4.w = acc4.w * sc + ((e0 * kf[0].w + e1 * kf[1].w) + (e2 * kf[2].w + e3 * kf[3].w));
        sum    = sum    * sc + ((e0 + e1) + (e2 + e3));
        m_run  = m_new;
    }

    // normalize
    float inv = 1.f / sum;
    acc4.x *= inv; acc4.y *= inv; acc4.z *= inv; acc4.w *= inv;
    float attn = __expf(myS - m_run) * inv;        // lane's own neighbor weight

    // rank (lax.top_k stable tie rule) — warp-local on adjusted scores
    int rank = 0;
#pragma unroll
    for (int i = 0; i < KNB; i++) {
        float si = __shfl_sync(0xffffffffu, myS, i);
        rank += (si > myS) || (si == myS && i < lane);
    }
    if (rank < TOPK) {
        if (__ldcg(&g_colmask[lane]) == 0) atomicOr(&g_colmask[lane], 1);
    }
    g_scores[(size_t)n * KNB + lane] = myS;
    out_ml[(size_t)n * KNB + lane]   = myMl;

    // xyz: lane j holds attn_j * xyz_j, butterfly-reduce 3 components
    float x0 = attn * xj0, x1 = attn * xj1, x2 = attn * xj2;
#pragma unroll
    for (int o = 16; o; o >>= 1) {
        x0 += __shfl_xor_sync(0xffffffffu, x0, o);
        x1 += __shfl_xor_sync(0xffffffffu, x1, o);
        x2 += __shfl_xor_sync(0xffffffffu, x2, o);
    }

    // outputs
    size_t ob = (size_t)n * 257;
    float4 f4 = __ldg(reinterpret_cast<const float4*>(feat + (size_t)n * CDIM) + lane);
    out_att[ob + lane * 4    ] = f4.x;
    out_att[ob + lane * 4 + 1] = f4.y;
    out_att[ob + lane * 4 + 2] = f4.z;
    out_att[ob + lane * 4 + 3] = f4.w;
    out_att[ob + 128 + lane * 4    ] = acc4.x;
    out_att[ob + 128 + lane * 4 + 1] = acc4.y;
    out_att[ob + 128 + lane * 4 + 2] = acc4.z;
    out_att[ob + 128 + lane * 4 + 3] = acc4.w;

    float p = fv.x * acc4.x + fv.y * acc4.y + fv.z * acc4.z + fv.w * acc4.w;
#pragma unroll
    for (int o = 16; o; o >>= 1) p += __shfl_xor_sync(0xffffffffu, p, o);
    if (lane == 0) {
        out_att[ob + 256] = p;                  // logit
        out_xyz[(size_t)n * 3    ] = x0;
        out_xyz[(size_t)n * 3 + 1] = x1;
        out_xyz[(size_t)n * 3 + 2] = x2;
    }
}

// ---------------- K3: fixup (computes needfix itself; rare path) ----------------
__global__ void __launch_bounds__(128) fixup_kernel(
    const float* __restrict__ knn_feat, const float* __restrict__ knn_xyz,
    float* __restrict__ out_xyz, float* __restrict__ out_att)
{
    __shared__ float attnS[KNB];
    __shared__ float redS[4];
    __shared__ int   colS[KNB];
    __shared__ int   needS;
    int tid = threadIdx.x, lane = tid & 31, warp = tid >> 5;
    if (tid < KNB) colS[tid] = g_colmask[tid];
    __syncthreads();
    if (tid == 0) {
        int nf = 0;
        for (int j = 0; j < KNB; j++) nf |= (colS[j] == 0);
        needS = nf;
    }
    __syncthreads();
    if (needS == 0) return;   // common case: every column covered

    for (int n = blockIdx.x; n < NROWS; n += gridDim.x) {
        if (tid < KNB) {
            float s  = g_scores[(size_t)n * KNB + tid];
            int inc  = colS[tid];
            float se = inc ? s : -3.0e38f;
            float m = se;
#pragma unroll
            for (int o = 16; o; o >>= 1) m = fmaxf(m, __shfl_xor_sync(0xffffffffu, m, o));
            float e = inc ? __expf(se - m) : 0.f;
            float ssum = e;
#pragma unroll
            for (int o = 16; o; o >>= 1) ssum += __shfl_xor_sync(0xffffffffu, ssum, o);
            attnS[tid] = e / ssum;
        }
        __syncthreads();

        float acc = 0.f;
#pragma unroll
        for (int j = 0; j < KNB; j++)
            acc += attnS[j] * knn_feat[(size_t)n * (KNB * CDIM) + j * CDIM + tid];

        size_t ob = (size_t)n * 257;
        out_att[ob + 128 + tid] = acc;

        float p = g_fW[(size_t)n * CDIM + tid] * acc;
#pragma unroll
        for (int o = 16; o; o >>= 1) p += __shfl_xor_sync(0xffffffffu, p, o);
        if (lane == 0) redS[warp] = p;
        __syncthreads();
        if (tid == 0) out_att[ob + 256] = redS[0] + redS[1] + redS[2] + redS[3];

        if (tid < 3) {
            float x = 0.f;
#pragma unroll
            for (int j = 0; j < KNB; j++)
                x += attnS[j] * knn_xyz[(size_t)n * (KNB * 3) + j * 3 + tid];
            out_xyz[(size_t)n * 3 + tid] = x;
        }
        __syncthreads();
    }
}

// ---------------- launch ----------------
extern "C" void kernel_launch(void* const* d_in, const int* in_sizes, int n_in,
                              void* d_out, int out_size) {
    const float* feat     = (const float*)d_in[0];          // [N,128]
    const float* knn_xyz  = (const float*)d_in[1];          // [N,32,3]
    const float* knn_feat = (const float*)d_in[2];          // [N,32,128]
    const void*  knn_mask = d_in[3];                        // [N,32] bool (width sniffed)
    const float* Wq       = (const float*)d_in[4];          // [128,128]
    const float* Wk       = (const float*)d_in[5];          // [128,128]
    const float* W        = (const float*)d_in[6];          // [128,128]

    float* out     = (float*)d_out;
    float* out_xyz = out;                                   // [N,3]
    float* out_att = out + (size_t)NROWS * 3;               // [N,257]
    float* out_ml  = out + (size_t)NROWS * 3 + (size_t)NROWS * 257;  // [N,32]

    prep_kernel<<<CDIM, CDIM>>>(Wq, Wk, W);
    sniff_kernel<<<512, 256>>>((const unsigned int*)knn_mask);

    cudaFuncSetAttribute(gemm_kernel, cudaFuncAttributeMaxDynamicSharedMemorySize,
                         GEMM_SMEM);
    gemm_kernel<<<NGB, 512, GEMM_SMEM>>>(feat);

    main_kernel<<<NROWS / 8, 256>>>(feat, knn_xyz, knn_feat, knn_mask,
                                    out_xyz, out_att, out_ml);

    fixup_kernel<<<2048, CDIM>>>(knn_feat, knn_xyz, out_xyz, out_att);
}